// round 16
// baseline (speedup 1.0000x reference)
#include <cuda_runtime.h>

#define NUM_CLASSES 1000
#define BATCH 8192
#define DD 4096
#define DENSE_ITEMS 4000               // 1000 classes * 4 column chunks
#define CE_ITEMS 1024                  // 8 rows per item
#define TOTAL_ITEMS (DENSE_ITEMS + CE_ITEMS)
#define GRID_BLOCKS 1184               // 148 SMs * 8 resident blocks @ 256thr/32reg
#define SROWS 64                       // staged indices (P[n>64] ~ 0; guarded)

// ---- graph-safe scratch (reset by prep / finalize each replay) ----
__device__ double g_loss1;
__device__ double g_loss2;
__device__ unsigned int g_done;
__device__ unsigned int g_ticket;
__device__ int    g_offsets[NUM_CLASSES + 1];
__device__ int    g_sorted [BATCH];

__device__ __forceinline__ float tanh_fast(float x) {
    float y;
    asm("tanh.approx.f32 %0, %1;" : "=f"(y) : "f"(x));
    return y;
}

__device__ __forceinline__ void sig_bce(float x, float y, float& sig, float& bce) {
    const float t  = tanh_fast(0.5f * x);
    sig = fmaf(0.5f, t, 0.5f);                         // sigmoid(x)
    const float sp = fmaf(0.5f, fabsf(t), 0.5f);       // sigmoid(|x|)
    bce = fmaxf(x, 0.f) - x * y - __logf(sp);          // stable BCE w/ logits
}

__device__ __forceinline__ float4 ldcs4(const float4* p) {
    float4 v;
    asm("ld.global.cs.v4.f32 {%0,%1,%2,%3}, [%4];"
        : "=f"(v.x), "=f"(v.y), "=f"(v.z), "=f"(v.w) : "l"(p));
    return v;
}

__device__ __forceinline__ void stcs(float* p, float v) {
    asm volatile("st.global.cs.f32 [%0], %1;" :: "l"(p), "f"(v));
}

// ---------------------------------------------------------------------------
// K1: prep — histogram + warp-shuffle scan + counting-sort scatter, 1 block.
// ---------------------------------------------------------------------------
__global__ __launch_bounds__(1024) void prep_kernel(const int* __restrict__ target,
                                                    float* __restrict__ out_ta) {
    __shared__ int hist[1024];
    __shared__ int wsum[32];
    const int tid  = threadIdx.x;
    const int lane = tid & 31, wid = tid >> 5;

    hist[tid] = 0;
    __syncthreads();

    int t[8];
    #pragma unroll
    for (int k = 0; k < 8; ++k) {
        t[k] = target[tid + k * 1024];
        atomicAdd(&hist[t[k]], 1);
    }
    __syncthreads();

    const int c = hist[tid];
    if (tid < NUM_CLASSES) out_ta[tid] = (float)c;

    int isc = c;
    #pragma unroll
    for (int o = 1; o < 32; o <<= 1) {
        const int v = __shfl_up_sync(0xffffffffu, isc, o);
        if (lane >= o) isc += v;
    }
    if (lane == 31) wsum[wid] = isc;
    __syncthreads();
    if (wid == 0) {
        int ws = wsum[lane];
        #pragma unroll
        for (int o = 1; o < 32; o <<= 1) {
            const int v = __shfl_up_sync(0xffffffffu, ws, o);
            if (lane >= o) ws += v;
        }
        wsum[lane] = ws;
    }
    __syncthreads();
    const int incl = isc + (wid ? wsum[wid - 1] : 0);
    const int excl = incl - c;

    if (tid < NUM_CLASSES) g_offsets[tid + 1] = incl;
    if (tid == 0) {
        g_offsets[0] = 0;
        g_loss1 = 0.0; g_loss2 = 0.0;
        g_done = 0u;   g_ticket = 0u;
    }

    hist[tid] = excl;                           // reuse as cursor
    __syncthreads();

    #pragma unroll
    for (int k = 0; k < 8; ++k) {
        const int p = atomicAdd(&hist[t[k]], 1);
        g_sorted[p] = tid + k * 1024;
    }
}

// ---------------------------------------------------------------------------
// K2: persistent fused main — blocks steal work items off a global ticket.
//   items [0, 4000)      : dense segsum+BCE, one (class, 1024-col chunk)
//   items [4000, 5024)   : cross-entropy, 8 rows each (one per warp)
// Last exiting block combines losses into out[0].
// ---------------------------------------------------------------------------
__global__ __launch_bounds__(256) void main_kernel(
        const float* __restrict__ logits,
        const int*   __restrict__ target,
        const float* __restrict__ dense_out,
        const float* __restrict__ dense_labels,
        float* __restrict__ out) {

    float* out_ds = out + 1;                               // [1000,4096]

    __shared__ int   s_item;
    __shared__ int   s_rows[SROWS];
    __shared__ float s_part[8];

    const int tid  = threadIdx.x;
    const int wid  = tid >> 5;
    const int lane = tid & 31;

    for (;;) {
        if (tid == 0)
            s_item = (int)atomicAdd(&g_ticket, 1u);
        __syncthreads();
        const int item = s_item;
        if (item >= TOTAL_ITEMS) break;

        if (item < DENSE_ITEMS) {
            // ================= DENSE SEGSUM + BCE =================
            const int c    = item >> 2;
            const int col4 = (item & 3) * 256 + tid;       // float4 idx 0..1023

            const float4 y = ((const float4*)(dense_labels + (size_t)c * DD))[col4];

            const int s = g_offsets[c];
            const int n = g_offsets[c + 1] - s;

            if (tid < n && tid < SROWS)
                s_rows[tid] = g_sorted[s + tid];
            __syncthreads();

            float4 acc = make_float4(0.f, 0.f, 0.f, 0.f);
            float  lsum = 0.f;
            float  sg, bc;

            int i = 0;
            for (; i + 4 <= n; i += 4) {                   // MLP=4 on row loads
                const int r0 = (i     < SROWS) ? s_rows[i]     : g_sorted[s + i];
                const int r1 = (i + 1 < SROWS) ? s_rows[i + 1] : g_sorted[s + i + 1];
                const int r2 = (i + 2 < SROWS) ? s_rows[i + 2] : g_sorted[s + i + 2];
                const int r3 = (i + 3 < SROWS) ? s_rows[i + 3] : g_sorted[s + i + 3];
                const float4 x0 = ldcs4((const float4*)(dense_out + (size_t)r0 * DD) + col4);
                const float4 x1 = ldcs4((const float4*)(dense_out + (size_t)r1 * DD) + col4);
                const float4 x2 = ldcs4((const float4*)(dense_out + (size_t)r2 * DD) + col4);
                const float4 x3 = ldcs4((const float4*)(dense_out + (size_t)r3 * DD) + col4);
                sig_bce(x0.x, y.x, sg, bc); acc.x += sg; lsum += bc;
                sig_bce(x0.y, y.y, sg, bc); acc.y += sg; lsum += bc;
                sig_bce(x0.z, y.z, sg, bc); acc.z += sg; lsum += bc;
                sig_bce(x0.w, y.w, sg, bc); acc.w += sg; lsum += bc;
                sig_bce(x1.x, y.x, sg, bc); acc.x += sg; lsum += bc;
                sig_bce(x1.y, y.y, sg, bc); acc.y += sg; lsum += bc;
                sig_bce(x1.z, y.z, sg, bc); acc.z += sg; lsum += bc;
                sig_bce(x1.w, y.w, sg, bc); acc.w += sg; lsum += bc;
                sig_bce(x2.x, y.x, sg, bc); acc.x += sg; lsum += bc;
                sig_bce(x2.y, y.y, sg, bc); acc.y += sg; lsum += bc;
                sig_bce(x2.z, y.z, sg, bc); acc.z += sg; lsum += bc;
                sig_bce(x2.w, y.w, sg, bc); acc.w += sg; lsum += bc;
                sig_bce(x3.x, y.x, sg, bc); acc.x += sg; lsum += bc;
                sig_bce(x3.y, y.y, sg, bc); acc.y += sg; lsum += bc;
                sig_bce(x3.z, y.z, sg, bc); acc.z += sg; lsum += bc;
                sig_bce(x3.w, y.w, sg, bc); acc.w += sg; lsum += bc;
            }
            for (; i < n; ++i) {
                const int r0 = (i < SROWS) ? s_rows[i] : g_sorted[s + i];
                const float4 x0 = ldcs4((const float4*)(dense_out + (size_t)r0 * DD) + col4);
                sig_bce(x0.x, y.x, sg, bc); acc.x += sg; lsum += bc;
                sig_bce(x0.y, y.y, sg, bc); acc.y += sg; lsum += bc;
                sig_bce(x0.z, y.z, sg, bc); acc.z += sg; lsum += bc;
                sig_bce(x0.w, y.w, sg, bc); acc.w += sg; lsum += bc;
            }

            float* dst = out_ds + (size_t)c * DD + (size_t)col4 * 4;  // 4B-aligned
            stcs(dst + 0, acc.x); stcs(dst + 1, acc.y);
            stcs(dst + 2, acc.z); stcs(dst + 3, acc.w);

            #pragma unroll
            for (int o = 16; o; o >>= 1)
                lsum += __shfl_xor_sync(0xffffffffu, lsum, o);
            if (lane == 0) s_part[wid] = lsum;
            __syncthreads();
            if (tid == 0) {
                float bs = 0.f;
                #pragma unroll
                for (int w = 0; w < 8; ++w) bs += s_part[w];
                atomicAdd(&g_loss2, (double)bs);
            }
            __syncthreads();          // smem safe for next item

        } else {
            // ==================== CROSS-ENTROPY ====================
            const int r = (item - DENSE_ITEMS) * 8 + wid;
            const float4* row = (const float4*)(logits + (size_t)r * NUM_CLASSES);

            float m = -1e30f, ssum = 0.f;
            #pragma unroll
            for (int k = 0; k < 8; ++k) {
                const int idx = k * 32 + lane;       // float4 index, 250 valid
                if (idx < NUM_CLASSES / 4) {
                    const float4 v = ldcs4(row + idx);
                    const float mv = fmaxf(fmaxf(v.x, v.y), fmaxf(v.z, v.w));
                    const float mn = fmaxf(m, mv);
                    ssum = ssum * __expf(m - mn)
                         + __expf(v.x - mn) + __expf(v.y - mn)
                         + __expf(v.z - mn) + __expf(v.w - mn);
                    m = mn;
                }
            }
            #pragma unroll
            for (int off = 16; off; off >>= 1) {
                const float mo = __shfl_xor_sync(0xffffffffu, m, off);
                const float so = __shfl_xor_sync(0xffffffffu, ssum, off);
                const float mn = fmaxf(m, mo);
                ssum = ssum * __expf(m - mn) + so * __expf(mo - mn);
                m = mn;
            }

            if (lane == 0)
                s_part[wid] = (__logf(ssum) + m)
                            - logits[(size_t)r * NUM_CLASSES + target[r]];
            __syncthreads();
            if (tid == 0) {
                float bs = 0.f;
                #pragma unroll
                for (int w = 0; w < 8; ++w) bs += s_part[w];
                atomicAdd(&g_loss1, (double)bs);
            }
            __syncthreads();          // smem safe for next item
        }
    }

    // --------------- last-exiting-block finalize ---------------
    if (tid == 0) {
        __threadfence();
        const unsigned int ticket = atomicAdd(&g_done, 1u);
        if (ticket == GRID_BLOCKS - 1) {
            __threadfence();
            const double l1 = g_loss1 / (double)BATCH;
            const double l2 = g_loss2 / ((double)BATCH * (double)DD);
            out[0] = (float)(0.5 * l1 + 0.5 * l2);
            g_done = 0u;              // reset for next graph replay
            g_loss1 = 0.0;
            g_loss2 = 0.0;
            g_ticket = 0u;            // (prep also resets; belt & braces)
        }
    }
}

// ---------------------------------------------------------------------------
extern "C" void kernel_launch(void* const* d_in, const int* in_sizes, int n_in,
                              void* d_out, int out_size) {
    const float* logits       = (const float*)d_in[0];
    const float* dense_out    = (const float*)d_in[1];
    const int*   target       = (const int*)  d_in[2];
    const float* dense_labels = (const float*)d_in[3];

    float* out    = (float*)d_out;
    float* out_ta = out + 1 + (size_t)NUM_CLASSES * DD;

    prep_kernel<<<1, 1024>>>(target, out_ta);
    main_kernel<<<GRID_BLOCKS, 256>>>(logits, target, dense_out,
                                      dense_labels, out);
}